// round 2
// baseline (speedup 1.0000x reference)
#include <cuda_runtime.h>
#include <cuda_bf16.h>

// Problem constants
#define BB 4
#define LL 2048
#define DD 1024
#define NQKV 1024   // QKV*H
#define MROWS (BB*LL)   // 8192

// Device scratch (allocation-free rule: __device__ globals)
__device__ float g_W[DD * DD];   // 2048 * (Wv @ Wo), [1024,1024]
__device__ float g_c[DD];        // 2048 * (bv @ Wo) + bo

// ---------------------------------------------------------------------------
// Fused bias: c[n] = 2048 * sum_j bv[j]*Wo[j,n] + bo[n]
// ---------------------------------------------------------------------------
__global__ void bias_kernel(const float* __restrict__ bv,
                            const float* __restrict__ Wo,
                            const float* __restrict__ bo,
                            float* __restrict__ c) {
    int n = blockIdx.x * blockDim.x + threadIdx.x;
    if (n >= DD) return;
    float s = 0.f;
    #pragma unroll 8
    for (int j = 0; j < NQKV; j++) {
        s += bv[j] * Wo[j * DD + n];
    }
    c[n] = 2048.0f * s + bo[n];
}

// ---------------------------------------------------------------------------
// Tiled fp32 SGEMM: C[M,N] = alpha * (A[M,K] @ B[K,N]) + (bias ? bias[n] : 0)
// BM=128 BN=128 BK=16, 256 threads, 8x8 per-thread microtile.
// Requires M%128==0, N%128==0, K%16==0 (all shapes here satisfy this).
// ---------------------------------------------------------------------------
#define BM 128
#define BN 128
#define BK 16
#define TM 8
#define TN 8

__global__ __launch_bounds__(256, 2)
void sgemm_kernel(const float* __restrict__ A,
                  const float* __restrict__ B,
                  const float* __restrict__ bias,
                  float* __restrict__ C,
                  int M, int N, int K, float alpha) {
    __shared__ float As[BK][BM];       // transposed A tile
    __shared__ float Bs[BK][BN];

    const int tid = threadIdx.x;
    const int blockRow = blockIdx.y * BM;
    const int blockCol = blockIdx.x * BN;

    // A tile load mapping: 128 rows x 16 cols = 512 float4; 2 per thread
    const int aRow = tid >> 2;          // 0..63
    const int aCol = (tid & 3) << 2;    // 0,4,8,12
    // B tile load mapping: 16 rows x 128 cols = 512 float4; 2 per thread
    const int bRow = tid >> 5;          // 0..7
    const int bCol = (tid & 31) << 2;   // 0..124 step 4

    // Compute mapping: 16x16 thread grid, each owns TMxTN
    const int tr = (tid >> 4) * TM;     // row offset in tile
    const int tc = (tid & 15) * TN;     // col offset in tile

    float acc[TM][TN];
    #pragma unroll
    for (int i = 0; i < TM; i++)
        #pragma unroll
        for (int j = 0; j < TN; j++)
            acc[i][j] = 0.f;

    const float* Aptr = A + (long)blockRow * K;
    const float* Bptr = B + blockCol;

    for (int k0 = 0; k0 < K; k0 += BK) {
        // Load A tile (transposed into smem)
        #pragma unroll
        for (int i = 0; i < 2; i++) {
            int r = aRow + i * 64;
            float4 v = *reinterpret_cast<const float4*>(Aptr + (long)r * K + k0 + aCol);
            As[aCol + 0][r] = v.x;
            As[aCol + 1][r] = v.y;
            As[aCol + 2][r] = v.z;
            As[aCol + 3][r] = v.w;
        }
        // Load B tile
        #pragma unroll
        for (int i = 0; i < 2; i++) {
            int r = bRow + i * 8;
            float4 v = *reinterpret_cast<const float4*>(Bptr + (long)(k0 + r) * N + bCol);
            *reinterpret_cast<float4*>(&Bs[r][bCol]) = v;
        }
        __syncthreads();

        #pragma unroll
        for (int k = 0; k < BK; k++) {
            float regM[TM], regN[TN];
            #pragma unroll
            for (int i = 0; i < TM; i++) regM[i] = As[k][tr + i];
            #pragma unroll
            for (int j = 0; j < TN; j++) regN[j] = Bs[k][tc + j];
            #pragma unroll
            for (int i = 0; i < TM; i++)
                #pragma unroll
                for (int j = 0; j < TN; j++)
                    acc[i][j] += regM[i] * regN[j];
        }
        __syncthreads();
    }

    // Epilogue
    #pragma unroll
    for (int i = 0; i < TM; i++) {
        long row = blockRow + tr + i;
        #pragma unroll
        for (int j = 0; j < TN; j += 4) {
            int col = blockCol + tc + j;
            float4 v;
            v.x = acc[i][j + 0] * alpha;
            v.y = acc[i][j + 1] * alpha;
            v.z = acc[i][j + 2] * alpha;
            v.w = acc[i][j + 3] * alpha;
            if (bias) {
                v.x += bias[col + 0];
                v.y += bias[col + 1];
                v.z += bias[col + 2];
                v.w += bias[col + 3];
            }
            *reinterpret_cast<float4*>(C + row * N + col) = v;
        }
    }
}

// ---------------------------------------------------------------------------
// Launch
// ---------------------------------------------------------------------------
extern "C" void kernel_launch(void* const* d_in, const int* in_sizes, int n_in,
                              void* d_out, int out_size) {
    const float* x  = (const float*)d_in[0];
    // d_in[1] encoder_x  — dead (softmax rows sum to 1; q,k fully contracted)
    // d_in[2] Wq, d_in[3] bq, d_in[4] Wk, d_in[5] bk — dead
    const float* Wv = (const float*)d_in[6];
    const float* bv = (const float*)d_in[7];
    const float* Wo = (const float*)d_in[8];
    const float* bo = (const float*)d_in[9];
    float* out = (float*)d_out;

    float* W;  cudaGetSymbolAddress((void**)&W, g_W);
    float* c;  cudaGetSymbolAddress((void**)&c, g_c);

    // 1) fused bias vector
    bias_kernel<<<(DD + 255) / 256, 256>>>(bv, Wo, bo, c);

    // 2) fused weight: W = 2048 * Wv @ Wo   [1024,1024]
    {
        dim3 grid(DD / BN, DD / BM);
        sgemm_kernel<<<grid, 256>>>(Wv, Wo, nullptr, W, DD, DD, DD, 2048.0f);
    }

    // 3) main GEMM: out[8192,1024] = x @ W + c
    {
        dim3 grid(DD / BN, MROWS / BM);
        sgemm_kernel<<<grid, 256>>>(x, W, c, out, MROWS, DD, DD, 1.0f);
    }
}

// round 3
// speedup vs baseline: 1.5219x; 1.5219x over previous
#include <cuda_runtime.h>
#include <cstdint>
#include <cstddef>

// Problem constants
#define BB 4
#define LL 2048
#define DD 1024
#define MROWS (BB*LL)   // 8192

// Device scratch (allocation-free rule: __device__ globals)
__device__ float g_W[DD * DD];       // 2048 * (Wv @ Wo)
__device__ float g_c[DD];            // 2048 * (bv @ Wo) + bo
__device__ float g_partial[64 * DD]; // bias split-j partials

// ---------------------------------------------------------------------------
// Bias: c[n] = 2048 * sum_j bv[j]*Wo[j,n] + bo[n]
// Split over j (64 chunks of 16) for parallelism + coalesced Wo reads.
// ---------------------------------------------------------------------------
__global__ void bias_partial_kernel(const float* __restrict__ bv,
                                    const float* __restrict__ Wo,
                                    float* __restrict__ part) {
    int n = blockIdx.x * 256 + threadIdx.x;
    int j0 = blockIdx.y * 16;
    float s = 0.f;
    #pragma unroll
    for (int j = 0; j < 16; j++)
        s += bv[j0 + j] * Wo[(size_t)(j0 + j) * DD + n];
    part[blockIdx.y * DD + n] = s;
}

__global__ void bias_reduce_kernel(const float* __restrict__ part,
                                   const float* __restrict__ bo,
                                   float* __restrict__ c) {
    int n = blockIdx.x * 256 + threadIdx.x;
    float s = 0.f;
    #pragma unroll
    for (int b = 0; b < 64; b++)
        s += part[b * DD + n];
    c[n] = 2048.0f * s + bo[n];
}

// ---------------------------------------------------------------------------
// tf32 tensor-core GEMM with 3-term precision split (fp32-accurate).
// C[M,N] = alpha * (A @ B) + bias[n]
// BM=128 BN=128 BK=16, 256 threads (8 warps as 2x4), warp tile 64x32,
// mma.sync.m16n8k8 tf32. Double-buffered smem, pad=8 -> conflict-free LDS.
// ---------------------------------------------------------------------------
__device__ __forceinline__ uint32_t f2tf(float x) {
    uint32_t r;
    asm("cvt.rna.tf32.f32 %0, %1;" : "=r"(r) : "f"(x));
    return r;
}

__device__ __forceinline__ void mma8(float c[4],
                                     uint32_t a0, uint32_t a1, uint32_t a2, uint32_t a3,
                                     uint32_t b0, uint32_t b1) {
    asm volatile(
        "mma.sync.aligned.m16n8k8.row.col.f32.tf32.tf32.f32 "
        "{%0,%1,%2,%3},{%4,%5,%6,%7},{%8,%9},{%0,%1,%2,%3};"
        : "+f"(c[0]), "+f"(c[1]), "+f"(c[2]), "+f"(c[3])
        : "r"(a0), "r"(a1), "r"(a2), "r"(a3), "r"(b0), "r"(b1));
}

#define PAD 8
#define SROW (128 + PAD)   // 136 floats per smem row

__global__ __launch_bounds__(256, 1)
void tf32_gemm(const float* __restrict__ A,
               const float* __restrict__ B,
               const float* __restrict__ bias,
               float* __restrict__ C,
               int M, int N, int K, float alpha) {
    __shared__ float As[2][16][SROW];   // [k][m], transposed A tile
    __shared__ float Bs[2][16][SROW];   // [k][n]

    const int tid  = threadIdx.x;
    const int lane = tid & 31;
    const int warp = tid >> 5;
    const int wm = warp >> 2;   // 0..1  (64 rows each)
    const int wn = warp & 3;    // 0..3  (32 cols each)

    const int blockRow = blockIdx.y * 128;
    const int blockCol = blockIdx.x * 128;

    // gmem load mapping
    const int aRow = tid >> 2;          // 0..63  (rows aRow, aRow+64)
    const int aCol = (tid & 3) << 2;    // 0,4,8,12
    const int bRow = tid >> 4;          // 0..15
    const int bCol = (tid & 15) << 2;   // 0..60 step 4 (cols bCol, bCol+64)

    const float* Ag = A + (size_t)blockRow * K;
    const float* Bg = B + blockCol;

    float acc[4][4][4];
    #pragma unroll
    for (int mt = 0; mt < 4; mt++)
        #pragma unroll
        for (int nt = 0; nt < 4; nt++)
            #pragma unroll
            for (int i = 0; i < 4; i++)
                acc[mt][nt][i] = 0.f;

    float4 ra0, ra1, rb0, rb1;

    // preload tile 0
    ra0 = *(const float4*)(Ag + (size_t)aRow * K + aCol);
    ra1 = *(const float4*)(Ag + (size_t)(aRow + 64) * K + aCol);
    rb0 = *(const float4*)(Bg + (size_t)bRow * N + bCol);
    rb1 = *(const float4*)(Bg + (size_t)bRow * N + bCol + 64);

    // store tile 0 to buffer 0 (A transposed)
    As[0][aCol + 0][aRow] = ra0.x;  As[0][aCol + 1][aRow] = ra0.y;
    As[0][aCol + 2][aRow] = ra0.z;  As[0][aCol + 3][aRow] = ra0.w;
    As[0][aCol + 0][aRow + 64] = ra1.x;  As[0][aCol + 1][aRow + 64] = ra1.y;
    As[0][aCol + 2][aRow + 64] = ra1.z;  As[0][aCol + 3][aRow + 64] = ra1.w;
    *(float4*)&Bs[0][bRow][bCol]      = rb0;
    *(float4*)&Bs[0][bRow][bCol + 64] = rb1;
    __syncthreads();

    const int nT = K / 16;
    const int r  = lane >> 2;   // 0..7
    const int cq = lane & 3;    // 0..3

    for (int t = 0; t < nT; t++) {
        const int cur = t & 1;

        // prefetch next tile into registers
        if (t + 1 < nT) {
            const int k0 = (t + 1) * 16;
            ra0 = *(const float4*)(Ag + (size_t)aRow * K + k0 + aCol);
            ra1 = *(const float4*)(Ag + (size_t)(aRow + 64) * K + k0 + aCol);
            rb0 = *(const float4*)(Bg + (size_t)(k0 + bRow) * N + bCol);
            rb1 = *(const float4*)(Bg + (size_t)(k0 + bRow) * N + bCol + 64);
        }

        // compute on current buffer: two k8 steps
        #pragma unroll
        for (int kk = 0; kk < 16; kk += 8) {
            uint32_t Ahi[4][4], Alo[4][4], Bhi[4][2], Blo[4][2];

            #pragma unroll
            for (int mt = 0; mt < 4; mt++) {
                const int m0 = wm * 64 + mt * 16 + r;
                float a0 = As[cur][kk + cq][m0];
                float a1 = As[cur][kk + cq][m0 + 8];
                float a2 = As[cur][kk + cq + 4][m0];
                float a3 = As[cur][kk + cq + 4][m0 + 8];
                Ahi[mt][0] = f2tf(a0);  Alo[mt][0] = __float_as_uint(a0 - __uint_as_float(Ahi[mt][0]));
                Ahi[mt][1] = f2tf(a1);  Alo[mt][1] = __float_as_uint(a1 - __uint_as_float(Ahi[mt][1]));
                Ahi[mt][2] = f2tf(a2);  Alo[mt][2] = __float_as_uint(a2 - __uint_as_float(Ahi[mt][2]));
                Ahi[mt][3] = f2tf(a3);  Alo[mt][3] = __float_as_uint(a3 - __uint_as_float(Ahi[mt][3]));
            }
            #pragma unroll
            for (int nt = 0; nt < 4; nt++) {
                const int n0 = wn * 32 + nt * 8 + r;
                float b0 = Bs[cur][kk + cq][n0];
                float b1 = Bs[cur][kk + cq + 4][n0];
                Bhi[nt][0] = f2tf(b0);  Blo[nt][0] = __float_as_uint(b0 - __uint_as_float(Bhi[nt][0]));
                Bhi[nt][1] = f2tf(b1);  Blo[nt][1] = __float_as_uint(b1 - __uint_as_float(Bhi[nt][1]));
            }

            #pragma unroll
            for (int mt = 0; mt < 4; mt++)
                #pragma unroll
                for (int nt = 0; nt < 4; nt++) {
                    mma8(acc[mt][nt], Ahi[mt][0], Ahi[mt][1], Ahi[mt][2], Ahi[mt][3],
                         Bhi[nt][0], Bhi[nt][1]);
                    mma8(acc[mt][nt], Ahi[mt][0], Ahi[mt][1], Ahi[mt][2], Ahi[mt][3],
                         Blo[nt][0], Blo[nt][1]);
                    mma8(acc[mt][nt], Alo[mt][0], Alo[mt][1], Alo[mt][2], Alo[mt][3],
                         Bhi[nt][0], Bhi[nt][1]);
                }
        }

        // store prefetched tile into other buffer
        if (t + 1 < nT) {
            const int nxt = cur ^ 1;
            As[nxt][aCol + 0][aRow] = ra0.x;  As[nxt][aCol + 1][aRow] = ra0.y;
            As[nxt][aCol + 2][aRow] = ra0.z;  As[nxt][aCol + 3][aRow] = ra0.w;
            As[nxt][aCol + 0][aRow + 64] = ra1.x;  As[nxt][aCol + 1][aRow + 64] = ra1.y;
            As[nxt][aCol + 2][aRow + 64] = ra1.z;  As[nxt][aCol + 3][aRow + 64] = ra1.w;
            *(float4*)&Bs[nxt][bRow][bCol]      = rb0;
            *(float4*)&Bs[nxt][bRow][bCol + 64] = rb1;
        }
        __syncthreads();
    }

    // Epilogue: c0,c1 -> (row, col..col+1); c2,c3 -> (row+8, col..col+1)
    #pragma unroll
    for (int mt = 0; mt < 4; mt++) {
        #pragma unroll
        for (int nt = 0; nt < 4; nt++) {
            const int row = blockRow + wm * 64 + mt * 16 + (lane >> 2);
            const int col = blockCol + wn * 32 + nt * 8 + 2 * (lane & 3);
            float b0 = 0.f, b1 = 0.f;
            if (bias) { b0 = bias[col]; b1 = bias[col + 1]; }
            float2 v0, v1;
            v0.x = acc[mt][nt][0] * alpha + b0;
            v0.y = acc[mt][nt][1] * alpha + b1;
            v1.x = acc[mt][nt][2] * alpha + b0;
            v1.y = acc[mt][nt][3] * alpha + b1;
            *(float2*)(C + (size_t)row * N + col)       = v0;
            *(float2*)(C + (size_t)(row + 8) * N + col) = v1;
        }
    }
}

// ---------------------------------------------------------------------------
// Launch
// out = x @ (2048*Wv@Wo) + (2048*bv@Wo + bo)
// (encoder_x/Wq/bq/Wk/bk are dead: softmax rows sum to 1 and the reference
// einsum contracts both q and k, so scores contribute exactly L = 2048.)
// ---------------------------------------------------------------------------
extern "C" void kernel_launch(void* const* d_in, const int* in_sizes, int n_in,
                              void* d_out, int out_size) {
    const float* x  = (const float*)d_in[0];
    const float* Wv = (const float*)d_in[6];
    const float* bv = (const float*)d_in[7];
    const float* Wo = (const float*)d_in[8];
    const float* bo = (const float*)d_in[9];
    float* out = (float*)d_out;

    float* W;  cudaGetSymbolAddress((void**)&W, g_W);
    float* c;  cudaGetSymbolAddress((void**)&c, g_c);
    float* p;  cudaGetSymbolAddress((void**)&p, g_partial);

    // 1) fused bias vector (split-j partials + reduce)
    {
        dim3 g1(DD / 256, 64);
        bias_partial_kernel<<<g1, 256>>>(bv, Wo, p);
        bias_reduce_kernel<<<DD / 256, 256>>>(p, bo, c);
    }

    // 2) fused weight: W = 2048 * Wv @ Wo   [1024,1024]
    {
        dim3 grid(DD / 128, DD / 128);
        tf32_gemm<<<grid, 256>>>(Wv, Wo, nullptr, W, DD, DD, DD, 2048.0f);
    }

    // 3) main GEMM: out[8192,1024] = x @ W + c
    {
        dim3 grid(DD / 128, MROWS / 128);
        tf32_gemm<<<grid, 256>>>(x, W, c, out, MROWS, DD, DD, 1.0f);
    }
}

// round 6
// speedup vs baseline: 3.1912x; 2.0969x over previous
#include <cuda_runtime.h>
#include <cuda_bf16.h>
#include <cstdint>
#include <cstddef>

// Problem constants
#define DD 1024
#define MROWS 8192

// ---------------------------------------------------------------------------
// Device scratch (allocation-free rule: __device__ globals)
// ---------------------------------------------------------------------------
__device__ unsigned short g_xhi[MROWS * DD];   // 16MB
__device__ unsigned short g_xlo[MROWS * DD];   // 16MB
__device__ unsigned short g_wvhi[DD * DD];     // 2MB
__device__ unsigned short g_wvlo[DD * DD];
__device__ unsigned short g_wothi[DD * DD];    // WoT = Wo^T splits
__device__ unsigned short g_wotlo[DD * DD];
__device__ unsigned short g_wthi[DD * DD];     // WT = (2048*Wv@Wo)^T splits
__device__ unsigned short g_wtlo[DD * DD];
__device__ float g_c[DD];
__device__ float g_partial[64 * DD];

// ---------------------------------------------------------------------------
// asm helpers (arch-neutral: mma.sync / ldmatrix / cp.async only)
// ---------------------------------------------------------------------------
__device__ __forceinline__ uint32_t smem_u32(const void* p) {
    uint32_t a;
    asm("{ .reg .u64 t; cvta.to.shared.u64 t, %1; cvt.u32.u64 %0, t; }" : "=r"(a) : "l"(p));
    return a;
}
#define CP16(dst, src) \
    asm volatile("cp.async.cg.shared.global [%0], [%1], 16;" :: "r"(dst), "l"(src))
#define CP_COMMIT()  asm volatile("cp.async.commit_group;" ::: "memory")
#define CP_WAIT1()   asm volatile("cp.async.wait_group 1;" ::: "memory")
#define CP_WAIT0()   asm volatile("cp.async.wait_group 0;" ::: "memory")

__device__ __forceinline__ void ldsm4(uint32_t& r0, uint32_t& r1, uint32_t& r2, uint32_t& r3,
                                      uint32_t addr) {
    asm volatile("ldmatrix.sync.aligned.m8n8.x4.shared.b16 {%0,%1,%2,%3}, [%4];"
                 : "=r"(r0), "=r"(r1), "=r"(r2), "=r"(r3) : "r"(addr));
}
__device__ __forceinline__ void mma16816(float c[4], const uint32_t a[4], const uint32_t b[2]) {
    asm volatile(
        "mma.sync.aligned.m16n8k16.row.col.f32.bf16.bf16.f32 "
        "{%0,%1,%2,%3},{%4,%5,%6,%7},{%8,%9},{%0,%1,%2,%3};"
        : "+f"(c[0]), "+f"(c[1]), "+f"(c[2]), "+f"(c[3])
        : "r"(a[0]), "r"(a[1]), "r"(a[2]), "r"(a[3]), "r"(b[0]), "r"(b[1]));
}

__device__ __forceinline__ uint32_t pack_lo_bf16x2(float l0, float l1) {
    uint32_t r;
    asm("cvt.rn.bf16x2.f32 %0, %1, %2;" : "=r"(r) : "f"(l1), "f"(l0));
    return r;
}
__device__ __forceinline__ float hi_part(float x) {
    return __uint_as_float(__float_as_uint(x) & 0xffff0000u);
}

// ---------------------------------------------------------------------------
// Split kernels: fp32 -> bf16 (hi = truncation, exact; lo = rn(x - hi))
// ---------------------------------------------------------------------------
__global__ void split_kernel(const float4* __restrict__ src,
                             uint2* __restrict__ dhi, uint2* __restrict__ dlo, int n4) {
    int i = blockIdx.x * 256 + threadIdx.x;
    if (i >= n4) return;
    float4 v = src[i];
    uint32_t u0 = __float_as_uint(v.x), u1 = __float_as_uint(v.y);
    uint32_t u2 = __float_as_uint(v.z), u3 = __float_as_uint(v.w);
    uint2 h;
    h.x = (u1 & 0xffff0000u) | (u0 >> 16);
    h.y = (u3 & 0xffff0000u) | (u2 >> 16);
    uint2 l;
    l.x = pack_lo_bf16x2(v.x - hi_part(v.x), v.y - hi_part(v.y));
    l.y = pack_lo_bf16x2(v.z - hi_part(v.z), v.w - hi_part(v.w));
    dhi[i] = h;
    dlo[i] = l;
}

// Transpose + split: dst[p][q] = split(src[q][p]), 1024x1024
__global__ void tsplit_kernel(const float* __restrict__ src,
                              unsigned short* __restrict__ dhi,
                              unsigned short* __restrict__ dlo) {
    __shared__ float t[32][33];
    const int bx = blockIdx.x * 32;   // output row tile / src col tile
    const int by = blockIdx.y * 32;   // output col tile / src row tile
    const int c = threadIdx.x & 31;
    const int r0 = threadIdx.x >> 5;  // 0..7
    #pragma unroll
    for (int i = 0; i < 4; i++) {
        int r = r0 + i * 8;
        t[r][c] = src[(size_t)(by + r) * DD + bx + c];
    }
    __syncthreads();
    #pragma unroll
    for (int i = 0; i < 4; i++) {
        int r = r0 + i * 8;
        float v = t[c][r];            // = src[by+c][bx+r]
        size_t o = (size_t)(bx + r) * DD + by + c;
        dhi[o] = (unsigned short)(__float_as_uint(v) >> 16);
        float lo = v - hi_part(v);
        dlo[o] = (unsigned short)(pack_lo_bf16x2(lo, 0.f) & 0xffffu);
    }
}

// ---------------------------------------------------------------------------
// Bias: c[n] = 2048 * sum_j bv[j]*Wo[j,n] + bo[n]
// ---------------------------------------------------------------------------
__global__ void bias_partial_kernel(const float* __restrict__ bv,
                                    const float* __restrict__ Wo,
                                    float* __restrict__ part) {
    int n = blockIdx.x * 256 + threadIdx.x;
    int j0 = blockIdx.y * 16;
    float s = 0.f;
    #pragma unroll
    for (int j = 0; j < 16; j++)
        s += bv[j0 + j] * Wo[(size_t)(j0 + j) * DD + n];
    part[blockIdx.y * DD + n] = s;
}
__global__ void bias_reduce_kernel(const float* __restrict__ part,
                                   const float* __restrict__ bo,
                                   float* __restrict__ c) {
    int n = blockIdx.x * 256 + threadIdx.x;
    float s = 0.f;
    #pragma unroll
    for (int b = 0; b < 64; b++)
        s += part[b * DD + n];
    c[n] = 2048.0f * s + bo[n];
}

// ---------------------------------------------------------------------------
// 3-term bf16 emulated fp32 GEMM (K=1024, N=1024 fixed).
//   C = alpha * (A @ B^T_layout) [+ bias]        A: [M][1024] bf16 hi/lo
//   B given as [n][k] bf16 hi/lo (i.e. B-matrix transposed, k contiguous)
// Terms: Ahi*Bhi + Ahi*Blo + Alo*Bhi  (flat 48-chunk loop, BK=64)
// If Cf != nullptr: write fp32 (+bias). Else: write truncation-split bf16
// pair (Chi, Clo) row-major — used to produce WT splits for the main pass.
// Tiles: BM x 128, 8 warps (2x4), warp tile (BM/2) x 32, mma m16n8k16.
// cp.async 3-stage pipeline, xor-swizzled smem, ldmatrix x4.
// ---------------------------------------------------------------------------
template <int BM>
__global__ __launch_bounds__(256, 2)
void gemm3(const __nv_bfloat16* __restrict__ Ahi, const __nv_bfloat16* __restrict__ Alo,
           const __nv_bfloat16* __restrict__ Bhi, const __nv_bfloat16* __restrict__ Blo,
           float* __restrict__ Cf, const float* __restrict__ bias,
           unsigned short* __restrict__ Chi, unsigned short* __restrict__ Clo,
           float alpha) {
    constexpr int MT  = BM / 32;             // m16 tiles per warp
    constexpr int STG = (BM + 128) * 128;    // bytes per stage (A tile + B tile)
    extern __shared__ char smv[];
    const uint32_t smb = smem_u32(smv);

    const int tid  = threadIdx.x;
    const int lane = tid & 31;
    const int warp = tid >> 5;
    const int wm = warp >> 2;                // 0..1
    const int wn = warp & 3;                 // 0..3
    const int blockRow = blockIdx.y * BM;
    const int blockCol = blockIdx.x * 128;

    const int l7  = lane & 7;
    const int lm  = lane & 15;
    const int hi4 = lane >> 4;

    auto issue = [&](int t, int buf) {
        const int seg = t >> 4;
        const int k0  = (t & 15) << 6;
        const __nv_bfloat16* Ap = (seg == 2) ? Alo : Ahi;
        const __nv_bfloat16* Bp = (seg == 1) ? Blo : Bhi;
        const uint32_t aB = smb + buf * STG;
        const uint32_t bB = aB + BM * 128;
        #pragma unroll
        for (int j = 0; j < BM / 32; j++) {
            int idx = j * 256 + tid;
            int row = idx >> 3, c = idx & 7;
            uint32_t dst = aB + row * 128 + ((c ^ (row & 7)) << 4);
            CP16(dst, Ap + (size_t)(blockRow + row) * DD + k0 + c * 8);
        }
        #pragma unroll
        for (int j = 0; j < 4; j++) {
            int idx = j * 256 + tid;
            int row = idx >> 3, c = idx & 7;
            uint32_t dst = bB + row * 128 + ((c ^ (row & 7)) << 4);
            CP16(dst, Bp + (size_t)(blockCol + row) * DD + k0 + c * 8);
        }
        CP_COMMIT();
    };

    float acc[MT][4][4];
    #pragma unroll
    for (int mt = 0; mt < MT; mt++)
        #pragma unroll
        for (int nt = 0; nt < 4; nt++)
            #pragma unroll
            for (int i = 0; i < 4; i++)
                acc[mt][nt][i] = 0.f;

    const int NT = 48;
    issue(0, 0);
    issue(1, 1);

    for (int t = 0; t < NT; t++) {
        const int buf = t % 3;
        if (t < NT - 1) CP_WAIT1(); else CP_WAIT0();
        __syncthreads();
        const uint32_t aB = smb + buf * STG;
        const uint32_t bB = aB + BM * 128;

        #pragma unroll
        for (int ks = 0; ks < 4; ks++) {
            uint32_t a[MT][4], b[4][2];
            #pragma unroll
            for (int mt = 0; mt < MT; mt++) {
                int m = wm * (BM / 2) + mt * 16 + lm;
                uint32_t ad = aB + m * 128 + ((((ks * 2 + hi4)) ^ l7) << 4);
                ldsm4(a[mt][0], a[mt][1], a[mt][2], a[mt][3], ad);
            }
            #pragma unroll
            for (int p = 0; p < 2; p++) {
                int im = lane >> 3;
                int nt = p * 2 + (im >> 1);
                int ch = (ks * 2 + (im & 1)) ^ l7;
                int n  = wn * 32 + nt * 8 + l7;
                uint32_t bd = bB + n * 128 + (ch << 4);
                ldsm4(b[p * 2][0], b[p * 2][1], b[p * 2 + 1][0], b[p * 2 + 1][1], bd);
            }
            #pragma unroll
            for (int mt = 0; mt < MT; mt++)
                #pragma unroll
                for (int nt = 0; nt < 4; nt++)
                    mma16816(acc[mt][nt], a[mt], b[nt]);
        }
        // issue stage t+2 into buffer (t+2)%3 (distinct from buffers in use)
        if (t + 2 < NT) issue(t + 2, (t + 2) % 3);
    }

    // Epilogue
    #pragma unroll
    for (int mt = 0; mt < MT; mt++) {
        #pragma unroll
        for (int nt = 0; nt < 4; nt++) {
            const int row = blockRow + wm * (BM / 2) + mt * 16 + (lane >> 2);
            const int col = blockCol + wn * 32 + nt * 8 + 2 * (lane & 3);
            float w0 = acc[mt][nt][0] * alpha;
            float w1 = acc[mt][nt][1] * alpha;
            float w2 = acc[mt][nt][2] * alpha;
            float w3 = acc[mt][nt][3] * alpha;
            if (Cf) {
                float b0 = bias[col], b1 = bias[col + 1];
                float2 v0 = make_float2(w0 + b0, w1 + b1);
                float2 v1 = make_float2(w2 + b0, w3 + b1);
                *(float2*)(Cf + (size_t)row * DD + col)       = v0;
                *(float2*)(Cf + (size_t)(row + 8) * DD + col) = v1;
            } else {
                uint32_t u0 = __float_as_uint(w0), u1 = __float_as_uint(w1);
                uint32_t u2 = __float_as_uint(w2), u3 = __float_as_uint(w3);
                *(uint32_t*)(Chi + (size_t)row * DD + col) =
                    (u1 & 0xffff0000u) | (u0 >> 16);
                *(uint32_t*)(Chi + (size_t)(row + 8) * DD + col) =
                    (u3 & 0xffff0000u) | (u2 >> 16);
                *(uint32_t*)(Clo + (size_t)row * DD + col) =
                    pack_lo_bf16x2(w0 - hi_part(w0), w1 - hi_part(w1));
                *(uint32_t*)(Clo + (size_t)(row + 8) * DD + col) =
                    pack_lo_bf16x2(w2 - hi_part(w2), w3 - hi_part(w3));
            }
        }
    }
}

// ---------------------------------------------------------------------------
// Launch:  out = x @ (2048*Wv@Wo) + (2048*bv@Wo + bo)
// (encoder_x/Wq/bq/Wk/bk dead: softmax rows sum to 1; the reference einsum
// contracts both q and k, so scores contribute exactly L = 2048.)
// tcgen05 is unavailable (harness PTX target is sm_103, not sm_103a), so all
// tensor work goes through arch-neutral mma.sync bf16 with 3-term splitting.
// ---------------------------------------------------------------------------
extern "C" void kernel_launch(void* const* d_in, const int* in_sizes, int n_in,
                              void* d_out, int out_size) {
    const float* x  = (const float*)d_in[0];
    const float* Wv = (const float*)d_in[6];
    const float* bv = (const float*)d_in[7];
    const float* Wo = (const float*)d_in[8];
    const float* bo = (const float*)d_in[9];
    float* out = (float*)d_out;

    unsigned short *xhi, *xlo, *wvhi, *wvlo, *wothi, *wotlo, *wthi, *wtlo;
    float *c, *p;
    cudaGetSymbolAddress((void**)&xhi,   g_xhi);
    cudaGetSymbolAddress((void**)&xlo,   g_xlo);
    cudaGetSymbolAddress((void**)&wvhi,  g_wvhi);
    cudaGetSymbolAddress((void**)&wvlo,  g_wvlo);
    cudaGetSymbolAddress((void**)&wothi, g_wothi);
    cudaGetSymbolAddress((void**)&wotlo, g_wotlo);
    cudaGetSymbolAddress((void**)&wthi,  g_wthi);
    cudaGetSymbolAddress((void**)&wtlo,  g_wtlo);
    cudaGetSymbolAddress((void**)&c,     g_c);
    cudaGetSymbolAddress((void**)&p,     g_partial);

    constexpr int SMEM64  = (64 + 128) * 128 * 3;    // 73728
    constexpr int SMEM128 = (128 + 128) * 128 * 3;   // 98304
    cudaFuncSetAttribute(gemm3<64>,  cudaFuncAttributeMaxDynamicSharedMemorySize, SMEM64);
    cudaFuncSetAttribute(gemm3<128>, cudaFuncAttributeMaxDynamicSharedMemorySize, SMEM128);

    // 1) splits
    split_kernel<<<(MROWS * DD / 4) / 256, 256>>>((const float4*)x,
                                                  (uint2*)xhi, (uint2*)xlo, MROWS * DD / 4);
    split_kernel<<<(DD * DD / 4) / 256, 256>>>((const float4*)Wv,
                                               (uint2*)wvhi, (uint2*)wvlo, DD * DD / 4);
    tsplit_kernel<<<dim3(32, 32), 256>>>(Wo, wothi, wotlo);

    // 2) fused bias vector
    bias_partial_kernel<<<dim3(DD / 256, 64), 256>>>(bv, Wo, p);
    bias_reduce_kernel<<<DD / 256, 256>>>(p, bo, c);

    // 3) WT = (2048 * Wv@Wo)^T as split bf16:  WT = 2048 * WoT @ Wv
    //    A = WoT splits (row-major [d2][j]), B-layout [n=d1][k=j] = Wv row-major.
    gemm3<64><<<dim3(8, 16), 256, SMEM64>>>(
        (const __nv_bfloat16*)wothi, (const __nv_bfloat16*)wotlo,
        (const __nv_bfloat16*)wvhi,  (const __nv_bfloat16*)wvlo,
        nullptr, nullptr, wthi, wtlo, 2048.0f);

    // 4) out[8192,1024] = x @ W + c   (B-layout [n][k] = WT splits)
    gemm3<128><<<dim3(8, 64), 256, SMEM128>>>(
        (const __nv_bfloat16*)xhi, (const __nv_bfloat16*)xlo,
        (const __nv_bfloat16*)wthi, (const __nv_bfloat16*)wtlo,
        out, c, nullptr, nullptr, 1.0f);
}

// round 7
// speedup vs baseline: 6.0997x; 1.9114x over previous
#include <cuda_runtime.h>
#include <cuda_bf16.h>
#include <cuda_fp16.h>
#include <cstdint>
#include <cstddef>

// Problem constants
#define DD 1024
#define MROWS 8192

// ---------------------------------------------------------------------------
// Device scratch (allocation-free rule: __device__ globals)
// ---------------------------------------------------------------------------
__device__ unsigned short g_xh[MROWS * DD];    // x as fp16, 16MB
__device__ unsigned short g_wvhi[DD * DD];     // Wv bf16 splits
__device__ unsigned short g_wvlo[DD * DD];
__device__ unsigned short g_wothi[DD * DD];    // WoT bf16 splits
__device__ unsigned short g_wotlo[DD * DD];
__device__ unsigned short g_wt[DD * DD];       // WT = (2048*Wv@Wo)^T as fp16
__device__ float g_c[DD];
__device__ float g_partial[64 * DD];

// ---------------------------------------------------------------------------
// asm helpers (arch-neutral: mma.sync / ldmatrix / cp.async only;
// tcgen05 unusable — harness PTX target is sm_103, not sm_103a)
// ---------------------------------------------------------------------------
__device__ __forceinline__ uint32_t smem_u32(const void* p) {
    uint32_t a;
    asm("{ .reg .u64 t; cvta.to.shared.u64 t, %1; cvt.u32.u64 %0, t; }" : "=r"(a) : "l"(p));
    return a;
}
#define CP16(dst, src) \
    asm volatile("cp.async.cg.shared.global [%0], [%1], 16;" :: "r"(dst), "l"(src))
#define CP_COMMIT()  asm volatile("cp.async.commit_group;" ::: "memory")
#define CP_WAIT1()   asm volatile("cp.async.wait_group 1;" ::: "memory")
#define CP_WAIT0()   asm volatile("cp.async.wait_group 0;" ::: "memory")

__device__ __forceinline__ void ldsm4(uint32_t& r0, uint32_t& r1, uint32_t& r2, uint32_t& r3,
                                      uint32_t addr) {
    asm volatile("ldmatrix.sync.aligned.m8n8.x4.shared.b16 {%0,%1,%2,%3}, [%4];"
                 : "=r"(r0), "=r"(r1), "=r"(r2), "=r"(r3) : "r"(addr));
}
__device__ __forceinline__ void mma_bf16(float c[4], const uint32_t a[4], const uint32_t b[2]) {
    asm volatile(
        "mma.sync.aligned.m16n8k16.row.col.f32.bf16.bf16.f32 "
        "{%0,%1,%2,%3},{%4,%5,%6,%7},{%8,%9},{%0,%1,%2,%3};"
        : "+f"(c[0]), "+f"(c[1]), "+f"(c[2]), "+f"(c[3])
        : "r"(a[0]), "r"(a[1]), "r"(a[2]), "r"(a[3]), "r"(b[0]), "r"(b[1]));
}
__device__ __forceinline__ void mma_f16(float c[4], const uint32_t a[4], const uint32_t b[2]) {
    asm volatile(
        "mma.sync.aligned.m16n8k16.row.col.f32.f16.f16.f32 "
        "{%0,%1,%2,%3},{%4,%5,%6,%7},{%8,%9},{%0,%1,%2,%3};"
        : "+f"(c[0]), "+f"(c[1]), "+f"(c[2]), "+f"(c[3])
        : "r"(a[0]), "r"(a[1]), "r"(a[2]), "r"(a[3]), "r"(b[0]), "r"(b[1]));
}

__device__ __forceinline__ uint32_t pack_lo_bf16x2(float l0, float l1) {
    uint32_t r;
    asm("cvt.rn.bf16x2.f32 %0, %1, %2;" : "=r"(r) : "f"(l1), "f"(l0));
    return r;
}
__device__ __forceinline__ uint32_t pack_f16x2(float v0, float v1) {
    uint32_t r;
    asm("cvt.rn.f16x2.f32 %0, %1, %2;" : "=r"(r) : "f"(v1), "f"(v0));
    return r;
}
__device__ __forceinline__ float hi_part(float x) {
    return __uint_as_float(__float_as_uint(x) & 0xffff0000u);
}

// ---------------------------------------------------------------------------
// x -> fp16 convert (vectorized)
// ---------------------------------------------------------------------------
__global__ void split16_kernel(const float4* __restrict__ src,
                               uint2* __restrict__ dst, int n4) {
    int i = blockIdx.x * 256 + threadIdx.x;
    if (i >= n4) return;
    float4 v = src[i];
    uint2 o;
    o.x = pack_f16x2(v.x, v.y);
    o.y = pack_f16x2(v.z, v.w);
    dst[i] = o;
}

// fp32 -> bf16 hi/lo split (hi = truncation, exact; lo = rn(x - hi))
__global__ void split_kernel(const float4* __restrict__ src,
                             uint2* __restrict__ dhi, uint2* __restrict__ dlo, int n4) {
    int i = blockIdx.x * 256 + threadIdx.x;
    if (i >= n4) return;
    float4 v = src[i];
    uint32_t u0 = __float_as_uint(v.x), u1 = __float_as_uint(v.y);
    uint32_t u2 = __float_as_uint(v.z), u3 = __float_as_uint(v.w);
    uint2 h;
    h.x = (u1 & 0xffff0000u) | (u0 >> 16);
    h.y = (u3 & 0xffff0000u) | (u2 >> 16);
    uint2 l;
    l.x = pack_lo_bf16x2(v.x - hi_part(v.x), v.y - hi_part(v.y));
    l.y = pack_lo_bf16x2(v.z - hi_part(v.z), v.w - hi_part(v.w));
    dhi[i] = h;
    dlo[i] = l;
}

// Transpose + bf16 split: dst[p][q] = split(src[q][p]), 1024x1024
__global__ void tsplit_kernel(const float* __restrict__ src,
                              unsigned short* __restrict__ dhi,
                              unsigned short* __restrict__ dlo) {
    __shared__ float t[32][33];
    const int bx = blockIdx.x * 32;
    const int by = blockIdx.y * 32;
    const int c = threadIdx.x & 31;
    const int r0 = threadIdx.x >> 5;
    #pragma unroll
    for (int i = 0; i < 4; i++) {
        int r = r0 + i * 8;
        t[r][c] = src[(size_t)(by + r) * DD + bx + c];
    }
    __syncthreads();
    #pragma unroll
    for (int i = 0; i < 4; i++) {
        int r = r0 + i * 8;
        float v = t[c][r];
        size_t o = (size_t)(bx + r) * DD + by + c;
        dhi[o] = (unsigned short)(__float_as_uint(v) >> 16);
        float lo = v - hi_part(v);
        dlo[o] = (unsigned short)(pack_lo_bf16x2(lo, 0.f) & 0xffffu);
    }
}

// ---------------------------------------------------------------------------
// Bias: c[n] = 2048 * sum_j bv[j]*Wo[j,n] + bo[n]
// ---------------------------------------------------------------------------
__global__ void bias_partial_kernel(const float* __restrict__ bv,
                                    const float* __restrict__ Wo,
                                    float* __restrict__ part) {
    int n = blockIdx.x * 256 + threadIdx.x;
    int j0 = blockIdx.y * 16;
    float s = 0.f;
    #pragma unroll
    for (int j = 0; j < 16; j++)
        s += bv[j0 + j] * Wo[(size_t)(j0 + j) * DD + n];
    part[blockIdx.y * DD + n] = s;
}
__global__ void bias_reduce_kernel(const float* __restrict__ part,
                                   const float* __restrict__ bo,
                                   float* __restrict__ c) {
    int n = blockIdx.x * 256 + threadIdx.x;
    float s = 0.f;
    #pragma unroll
    for (int b = 0; b < 64; b++)
        s += part[b * DD + n];
    c[n] = 2048.0f * s + bo[n];
}

// ---------------------------------------------------------------------------
// 3-term bf16 emulated fp32 GEMM for the weight precompute (K=1024, N=1024).
// Writes C as fp16 row-major (WT for the main pass). BM=64, warp tile 32x32.
// ---------------------------------------------------------------------------
__global__ __launch_bounds__(256, 2)
void gemm3_w(const __nv_bfloat16* __restrict__ Ahi, const __nv_bfloat16* __restrict__ Alo,
             const __nv_bfloat16* __restrict__ Bhi, const __nv_bfloat16* __restrict__ Blo,
             unsigned short* __restrict__ Ch, float alpha) {
    constexpr int BM = 64;
    constexpr int MT = BM / 32;
    constexpr int STG = (BM + 128) * 128;
    extern __shared__ char smv[];
    const uint32_t smb = smem_u32(smv);

    const int tid  = threadIdx.x;
    const int lane = tid & 31;
    const int warp = tid >> 5;
    const int wm = warp >> 2;
    const int wn = warp & 3;
    const int blockRow = blockIdx.y * BM;
    const int blockCol = blockIdx.x * 128;

    const int l7  = lane & 7;
    const int lm  = lane & 15;
    const int hi4 = lane >> 4;

    auto issue = [&](int t, int buf) {
        const int seg = t >> 4;
        const int k0  = (t & 15) << 6;
        const __nv_bfloat16* Ap = (seg == 2) ? Alo : Ahi;
        const __nv_bfloat16* Bp = (seg == 1) ? Blo : Bhi;
        const uint32_t aB = smb + buf * STG;
        const uint32_t bB = aB + BM * 128;
        #pragma unroll
        for (int j = 0; j < BM / 32; j++) {
            int idx = j * 256 + tid;
            int row = idx >> 3, c = idx & 7;
            uint32_t dst = aB + row * 128 + ((c ^ (row & 7)) << 4);
            CP16(dst, Ap + (size_t)(blockRow + row) * DD + k0 + c * 8);
        }
        #pragma unroll
        for (int j = 0; j < 4; j++) {
            int idx = j * 256 + tid;
            int row = idx >> 3, c = idx & 7;
            uint32_t dst = bB + row * 128 + ((c ^ (row & 7)) << 4);
            CP16(dst, Bp + (size_t)(blockCol + row) * DD + k0 + c * 8);
        }
        CP_COMMIT();
    };

    float acc[MT][4][4];
    #pragma unroll
    for (int mt = 0; mt < MT; mt++)
        #pragma unroll
        for (int nt = 0; nt < 4; nt++)
            #pragma unroll
            for (int i = 0; i < 4; i++)
                acc[mt][nt][i] = 0.f;

    const int NT = 48;
    issue(0, 0);
    issue(1, 1);

    for (int t = 0; t < NT; t++) {
        const int buf = t % 3;
        if (t < NT - 1) CP_WAIT1(); else CP_WAIT0();
        __syncthreads();
        const uint32_t aB = smb + buf * STG;
        const uint32_t bB = aB + BM * 128;

        #pragma unroll
        for (int ks = 0; ks < 4; ks++) {
            uint32_t a[MT][4], b[4][2];
            #pragma unroll
            for (int mt = 0; mt < MT; mt++) {
                int m = wm * (BM / 2) + mt * 16 + lm;
                uint32_t ad = aB + m * 128 + ((((ks * 2 + hi4)) ^ l7) << 4);
                ldsm4(a[mt][0], a[mt][1], a[mt][2], a[mt][3], ad);
            }
            #pragma unroll
            for (int p = 0; p < 2; p++) {
                int im = lane >> 3;
                int nt = p * 2 + (im >> 1);
                int ch = (ks * 2 + (im & 1)) ^ l7;
                int n  = wn * 32 + nt * 8 + l7;
                uint32_t bd = bB + n * 128 + (ch << 4);
                ldsm4(b[p * 2][0], b[p * 2][1], b[p * 2 + 1][0], b[p * 2 + 1][1], bd);
            }
            #pragma unroll
            for (int mt = 0; mt < MT; mt++)
                #pragma unroll
                for (int nt = 0; nt < 4; nt++)
                    mma_bf16(acc[mt][nt], a[mt], b[nt]);
        }
        if (t + 2 < NT) issue(t + 2, (t + 2) % 3);
    }

    // Epilogue: write fp16 WT
    #pragma unroll
    for (int mt = 0; mt < MT; mt++) {
        #pragma unroll
        for (int nt = 0; nt < 4; nt++) {
            const int row = blockRow + wm * (BM / 2) + mt * 16 + (lane >> 2);
            const int col = blockCol + wn * 32 + nt * 8 + 2 * (lane & 3);
            float w0 = acc[mt][nt][0] * alpha;
            float w1 = acc[mt][nt][1] * alpha;
            float w2 = acc[mt][nt][2] * alpha;
            float w3 = acc[mt][nt][3] * alpha;
            *(uint32_t*)(Ch + (size_t)row * DD + col)       = pack_f16x2(w0, w1);
            *(uint32_t*)(Ch + (size_t)(row + 8) * DD + col) = pack_f16x2(w2, w3);
        }
    }
}

// ---------------------------------------------------------------------------
// Single-term fp16 main GEMM: C[M,1024] = A@B^T_layout + bias
// A: [M][1024] fp16 row-major. B: [n][k] fp16 (k contiguous). K=1024, 16 chunks.
// BM=128 x BN=128, 8 warps (2x4), warp tile 64x32, 3-stage cp.async pipeline.
// ---------------------------------------------------------------------------
__global__ __launch_bounds__(256, 2)
void gemm_f16_main(const __half* __restrict__ A, const __half* __restrict__ B,
                   const float* __restrict__ bias, float* __restrict__ C) {
    constexpr int BM = 128;
    constexpr int MT = BM / 32;              // 4
    constexpr int STG = (BM + 128) * 128;    // 32KB
    extern __shared__ char smv[];
    const uint32_t smb = smem_u32(smv);

    const int tid  = threadIdx.x;
    const int lane = tid & 31;
    const int warp = tid >> 5;
    const int wm = warp >> 2;
    const int wn = warp & 3;
    const int blockRow = blockIdx.y * BM;
    const int blockCol = blockIdx.x * 128;

    const int l7  = lane & 7;
    const int lm  = lane & 15;
    const int hi4 = lane >> 4;

    auto issue = [&](int t, int buf) {
        const int k0 = t << 6;
        const uint32_t aB = smb + buf * STG;
        const uint32_t bB = aB + BM * 128;
        #pragma unroll
        for (int j = 0; j < BM / 32; j++) {
            int idx = j * 256 + tid;
            int row = idx >> 3, c = idx & 7;
            uint32_t dst = aB + row * 128 + ((c ^ (row & 7)) << 4);
            CP16(dst, A + (size_t)(blockRow + row) * DD + k0 + c * 8);
        }
        #pragma unroll
        for (int j = 0; j < 4; j++) {
            int idx = j * 256 + tid;
            int row = idx >> 3, c = idx & 7;
            uint32_t dst = bB + row * 128 + ((c ^ (row & 7)) << 4);
            CP16(dst, B + (size_t)(blockCol + row) * DD + k0 + c * 8);
        }
        CP_COMMIT();
    };

    float acc[MT][4][4];
    #pragma unroll
    for (int mt = 0; mt < MT; mt++)
        #pragma unroll
        for (int nt = 0; nt < 4; nt++)
            #pragma unroll
            for (int i = 0; i < 4; i++)
                acc[mt][nt][i] = 0.f;

    const int NT = 16;
    issue(0, 0);
    issue(1, 1);

    for (int t = 0; t < NT; t++) {
        const int buf = t % 3;
        if (t < NT - 1) CP_WAIT1(); else CP_WAIT0();
        __syncthreads();
        const uint32_t aB = smb + buf * STG;
        const uint32_t bB = aB + BM * 128;

        #pragma unroll
        for (int ks = 0; ks < 4; ks++) {
            uint32_t a[MT][4], b[4][2];
            #pragma unroll
            for (int mt = 0; mt < MT; mt++) {
                int m = wm * (BM / 2) + mt * 16 + lm;
                uint32_t ad = aB + m * 128 + ((((ks * 2 + hi4)) ^ l7) << 4);
                ldsm4(a[mt][0], a[mt][1], a[mt][2], a[mt][3], ad);
            }
            #pragma unroll
            for (int p = 0; p < 2; p++) {
                int im = lane >> 3;
                int nt = p * 2 + (im >> 1);
                int ch = (ks * 2 + (im & 1)) ^ l7;
                int n  = wn * 32 + nt * 8 + l7;
                uint32_t bd = bB + n * 128 + (ch << 4);
                ldsm4(b[p * 2][0], b[p * 2][1], b[p * 2 + 1][0], b[p * 2 + 1][1], bd);
            }
            #pragma unroll
            for (int mt = 0; mt < MT; mt++)
                #pragma unroll
                for (int nt = 0; nt < 4; nt++)
                    mma_f16(acc[mt][nt], a[mt], b[nt]);
        }
        if (t + 2 < NT) issue(t + 2, (t + 2) % 3);
    }

    // Epilogue: fp32 + bias
    #pragma unroll
    for (int mt = 0; mt < MT; mt++) {
        #pragma unroll
        for (int nt = 0; nt < 4; nt++) {
            const int row = blockRow + wm * (BM / 2) + mt * 16 + (lane >> 2);
            const int col = blockCol + wn * 32 + nt * 8 + 2 * (lane & 3);
            float b0 = bias[col], b1 = bias[col + 1];
            float2 v0 = make_float2(acc[mt][nt][0] + b0, acc[mt][nt][1] + b1);
            float2 v1 = make_float2(acc[mt][nt][2] + b0, acc[mt][nt][3] + b1);
            *(float2*)(C + (size_t)row * DD + col)       = v0;
            *(float2*)(C + (size_t)(row + 8) * DD + col) = v1;
        }
    }
}

// ---------------------------------------------------------------------------
// Launch:  out = x @ (2048*Wv@Wo) + (2048*bv@Wo + bo)
// (encoder_x/Wq/bq/Wk/bk dead: softmax rows sum to 1; the reference einsum
// contracts both q and k, so scores contribute exactly L = 2048.)
// W precomputed fp32-accurately (bf16 3-term) then rounded to fp16; main GEMM
// is single-term fp16 (predicted aggregate rel_err ~4e-4 < 1e-3 gate).
// ---------------------------------------------------------------------------
extern "C" void kernel_launch(void* const* d_in, const int* in_sizes, int n_in,
                              void* d_out, int out_size) {
    const float* x  = (const float*)d_in[0];
    const float* Wv = (const float*)d_in[6];
    const float* bv = (const float*)d_in[7];
    const float* Wo = (const float*)d_in[8];
    const float* bo = (const float*)d_in[9];
    float* out = (float*)d_out;

    unsigned short *xh, *wvhi, *wvlo, *wothi, *wotlo, *wt;
    float *c, *p;
    cudaGetSymbolAddress((void**)&xh,    g_xh);
    cudaGetSymbolAddress((void**)&wvhi,  g_wvhi);
    cudaGetSymbolAddress((void**)&wvlo,  g_wvlo);
    cudaGetSymbolAddress((void**)&wothi, g_wothi);
    cudaGetSymbolAddress((void**)&wotlo, g_wotlo);
    cudaGetSymbolAddress((void**)&wt,    g_wt);
    cudaGetSymbolAddress((void**)&c,     g_c);
    cudaGetSymbolAddress((void**)&p,     g_partial);

    constexpr int SMEM64  = (64 + 128) * 128 * 3;    // 73728
    constexpr int SMEM128 = (128 + 128) * 128 * 3;   // 98304
    cudaFuncSetAttribute(gemm3_w,       cudaFuncAttributeMaxDynamicSharedMemorySize, SMEM64);
    cudaFuncSetAttribute(gemm_f16_main, cudaFuncAttributeMaxDynamicSharedMemorySize, SMEM128);

    // 1) weight-side splits + bias (small, front-loaded)
    split_kernel<<<(DD * DD / 4) / 256, 256>>>((const float4*)Wv,
                                               (uint2*)wvhi, (uint2*)wvlo, DD * DD / 4);
    tsplit_kernel<<<dim3(32, 32), 256>>>(Wo, wothi, wotlo);
    bias_partial_kernel<<<dim3(DD / 256, 64), 256>>>(bv, Wo, p);
    bias_reduce_kernel<<<DD / 256, 256>>>(p, bo, c);

    // 2) x -> fp16
    split16_kernel<<<(MROWS * DD / 4) / 256, 256>>>((const float4*)x,
                                                    (uint2*)xh, MROWS * DD / 4);

    // 3) WT = (2048 * Wv@Wo)^T  ->  fp16   (A = WoT splits, B-layout = Wv rows)
    gemm3_w<<<dim3(8, 16), 256, SMEM64>>>(
        (const __nv_bfloat16*)wothi, (const __nv_bfloat16*)wotlo,
        (const __nv_bfloat16*)wvhi,  (const __nv_bfloat16*)wvlo,
        wt, 2048.0f);

    // 4) out[8192,1024] = x_fp16 @ W_fp16 + c
    gemm_f16_main<<<dim3(8, 64), 256, SMEM128>>>(
        (const __half*)xh, (const __half*)wt, c, out);
}

// round 8
// speedup vs baseline: 7.3039x; 1.1974x over previous
#include <cuda_runtime.h>
#include <cuda_fp16.h>
#include <cstdint>
#include <cstddef>

// Problem constants
#define DD 1024
#define MROWS 8192

// ---------------------------------------------------------------------------
// Device scratch (allocation-free rule: __device__ globals)
// ---------------------------------------------------------------------------
__device__ unsigned short g_xh[MROWS * DD];   // x as fp16 (16MB)
__device__ unsigned short g_wv16[DD * DD];    // Wv as fp16
__device__ unsigned short g_wot16[DD * DD];   // Wo^T as fp16
__device__ unsigned short g_wt[DD * DD];      // WT = (2048*Wv@Wo)^T as fp16
__device__ float g_c[DD];                     // 2048*(bv@Wo) + bo

// ---------------------------------------------------------------------------
// asm helpers (arch-neutral: mma.sync / ldmatrix / cp.async;
// tcgen05 unusable — harness PTX target is sm_103, not sm_103a)
// ---------------------------------------------------------------------------
__device__ __forceinline__ uint32_t smem_u32(const void* p) {
    uint32_t a;
    asm("{ .reg .u64 t; cvta.to.shared.u64 t, %1; cvt.u32.u64 %0, t; }" : "=r"(a) : "l"(p));
    return a;
}
#define CP16(dst, src) \
    asm volatile("cp.async.cg.shared.global [%0], [%1], 16;" :: "r"(dst), "l"(src))
#define CP_COMMIT()  asm volatile("cp.async.commit_group;" ::: "memory")
#define CP_WAIT1()   asm volatile("cp.async.wait_group 1;" ::: "memory")
#define CP_WAIT0()   asm volatile("cp.async.wait_group 0;" ::: "memory")

__device__ __forceinline__ void ldsm4(uint32_t& r0, uint32_t& r1, uint32_t& r2, uint32_t& r3,
                                      uint32_t addr) {
    asm volatile("ldmatrix.sync.aligned.m8n8.x4.shared.b16 {%0,%1,%2,%3}, [%4];"
                 : "=r"(r0), "=r"(r1), "=r"(r2), "=r"(r3) : "r"(addr));
}
__device__ __forceinline__ void mma_f16(float c[4], const uint32_t a[4], const uint32_t b[2]) {
    asm volatile(
        "mma.sync.aligned.m16n8k16.row.col.f32.f16.f16.f32 "
        "{%0,%1,%2,%3},{%4,%5,%6,%7},{%8,%9},{%0,%1,%2,%3};"
        : "+f"(c[0]), "+f"(c[1]), "+f"(c[2]), "+f"(c[3])
        : "r"(a[0]), "r"(a[1]), "r"(a[2]), "r"(a[3]), "r"(b[0]), "r"(b[1]));
}
__device__ __forceinline__ uint32_t pack_f16x2(float v0, float v1) {
    uint32_t r;
    asm("cvt.rn.f16x2.f32 %0, %1, %2;" : "=r"(r) : "f"(v1), "f"(v0));
    return r;
}

// ---------------------------------------------------------------------------
// Fused prep kernel (one launch, blocks partitioned by role):
//   [0,1024)      x -> fp16              (2M float4)
//   [1024,1152)   Wv -> fp16             (256K float4)
//   [1152,2176)   Wo^T -> fp16           (32x32 transpose tiles)
//   [2176,2208)   bias c = 2048*bv@Wo+bo (32 n-cols per block)
// ---------------------------------------------------------------------------
#define PREP_X_BLKS   1024
#define PREP_WV_BLKS  128
#define PREP_WOT_BLKS 1024
#define PREP_B_BLKS   32
#define PREP_BLKS (PREP_X_BLKS + PREP_WV_BLKS + PREP_WOT_BLKS + PREP_B_BLKS)

__global__ __launch_bounds__(256)
void prep_kernel(const float4* __restrict__ x,
                 const float4* __restrict__ Wv,
                 const float*  __restrict__ Wo,
                 const float*  __restrict__ bv,
                 const float*  __restrict__ bo,
                 uint2* __restrict__ xh, uint2* __restrict__ wv16,
                 unsigned short* __restrict__ wot16, float* __restrict__ c) {
    const int bid = blockIdx.x;
    const int tid = threadIdx.x;

    if (bid < PREP_X_BLKS) {
        // x convert: 2048 float4 per block
        int base = bid * 2048 + tid;
        #pragma unroll
        for (int i = 0; i < 8; i++) {
            int idx = base + i * 256;
            float4 v = x[idx];
            uint2 o;
            o.x = pack_f16x2(v.x, v.y);
            o.y = pack_f16x2(v.z, v.w);
            xh[idx] = o;
        }
        return;
    }
    if (bid < PREP_X_BLKS + PREP_WV_BLKS) {
        int base = (bid - PREP_X_BLKS) * 2048 + tid;
        #pragma unroll
        for (int i = 0; i < 8; i++) {
            int idx = base + i * 256;
            float4 v = Wv[idx];
            uint2 o;
            o.x = pack_f16x2(v.x, v.y);
            o.y = pack_f16x2(v.z, v.w);
            ((uint2*)wv16)[idx] = o;
        }
        return;
    }
    if (bid < PREP_X_BLKS + PREP_WV_BLKS + PREP_WOT_BLKS) {
        // Wo^T tile: wot16[p][q] = (fp16) Wo[q][p]
        __shared__ float t[32][33];
        const int local = bid - (PREP_X_BLKS + PREP_WV_BLKS);
        const int bx = (local & 31) * 32;   // output row base (= src col)
        const int by = (local >> 5) * 32;   // output col base (= src row)
        const int cc = tid & 31;
        const int r0 = tid >> 5;
        #pragma unroll
        for (int i = 0; i < 4; i++) {
            int r = r0 + i * 8;
            t[r][cc] = Wo[(size_t)(by + r) * DD + bx + cc];
        }
        __syncthreads();
        #pragma unroll
        for (int i = 0; i < 4; i++) {
            int r = r0 + i * 8;
            float v = t[cc][r];             // = Wo[by+cc][bx+r]
            wot16[(size_t)(bx + r) * DD + by + cc] =
                (unsigned short)(pack_f16x2(v, 0.f) & 0xffffu);
        }
        return;
    }
    // bias: 32 n-columns per block; 8 j-groups x 32 n threads
    {
        __shared__ float part[8][32];
        const int n0 = (bid - (PREP_X_BLKS + PREP_WV_BLKS + PREP_WOT_BLKS)) * 32;
        const int nl = tid & 31;
        const int jg = tid >> 5;            // 0..7, 128 j each
        float s = 0.f;
        #pragma unroll 4
        for (int j = jg * 128; j < jg * 128 + 128; j++)
            s += bv[j] * Wo[(size_t)j * DD + n0 + nl];
        part[jg][nl] = s;
        __syncthreads();
        if (tid < 32) {
            float acc = 0.f;
            #pragma unroll
            for (int g = 0; g < 8; g++) acc += part[g][nl];
            c[n0 + nl] = 2048.0f * acc + bo[n0 + nl];
        }
    }
}

// ---------------------------------------------------------------------------
// fp16 single-term GEMM (K=1024, N tile 128). Template:
//   BM:        block rows
//   WRITE_F16: epilogue writes fp16 (alpha-scaled) vs fp32 (+bias)
// A: [M][1024] fp16 row-major; B: [n][k] fp16, k contiguous.
// 8 warps (2x4), warp tile (BM/2) x 32, 3-stage cp.async, xor-swizzled smem.
// ---------------------------------------------------------------------------
template <int BM, bool WRITE_F16>
__global__ __launch_bounds__(256, 2)
void gemm_f16(const __half* __restrict__ A, const __half* __restrict__ B,
              const float* __restrict__ bias, float* __restrict__ Cf,
              unsigned short* __restrict__ Ch, float alpha) {
    constexpr int MT = BM / 32;
    constexpr int STG = (BM + 128) * 128;
    extern __shared__ char smv[];
    const uint32_t smb = smem_u32(smv);

    const int tid  = threadIdx.x;
    const int lane = tid & 31;
    const int warp = tid >> 5;
    const int wm = warp >> 2;
    const int wn = warp & 3;
    const int blockRow = blockIdx.y * BM;
    const int blockCol = blockIdx.x * 128;

    const int l7  = lane & 7;
    const int lm  = lane & 15;
    const int hi4 = lane >> 4;

    auto issue = [&](int t, int buf) {
        const int k0 = t << 6;
        const uint32_t aB = smb + buf * STG;
        const uint32_t bB = aB + BM * 128;
        #pragma unroll
        for (int j = 0; j < BM / 32; j++) {
            int idx = j * 256 + tid;
            int row = idx >> 3, cc = idx & 7;
            uint32_t dst = aB + row * 128 + ((cc ^ (row & 7)) << 4);
            CP16(dst, A + (size_t)(blockRow + row) * DD + k0 + cc * 8);
        }
        #pragma unroll
        for (int j = 0; j < 4; j++) {
            int idx = j * 256 + tid;
            int row = idx >> 3, cc = idx & 7;
            uint32_t dst = bB + row * 128 + ((cc ^ (row & 7)) << 4);
            CP16(dst, B + (size_t)(blockCol + row) * DD + k0 + cc * 8);
        }
        CP_COMMIT();
    };

    float acc[MT][4][4];
    #pragma unroll
    for (int mt = 0; mt < MT; mt++)
        #pragma unroll
        for (int nt = 0; nt < 4; nt++)
            #pragma unroll
            for (int i = 0; i < 4; i++)
                acc[mt][nt][i] = 0.f;

    const int NT = 16;
    issue(0, 0);
    issue(1, 1);

    for (int t = 0; t < NT; t++) {
        const int buf = t % 3;
        if (t < NT - 1) CP_WAIT1(); else CP_WAIT0();
        __syncthreads();
        const uint32_t aB = smb + buf * STG;
        const uint32_t bB = aB + BM * 128;

        #pragma unroll
        for (int ks = 0; ks < 4; ks++) {
            uint32_t a[MT][4], b[4][2];
            #pragma unroll
            for (int mt = 0; mt < MT; mt++) {
                int m = wm * (BM / 2) + mt * 16 + lm;
                uint32_t ad = aB + m * 128 + ((((ks * 2 + hi4)) ^ l7) << 4);
                ldsm4(a[mt][0], a[mt][1], a[mt][2], a[mt][3], ad);
            }
            #pragma unroll
            for (int p = 0; p < 2; p++) {
                int im = lane >> 3;
                int nt = p * 2 + (im >> 1);
                int ch = (ks * 2 + (im & 1)) ^ l7;
                int n  = wn * 32 + nt * 8 + l7;
                uint32_t bd = bB + n * 128 + (ch << 4);
                ldsm4(b[p * 2][0], b[p * 2][1], b[p * 2 + 1][0], b[p * 2 + 1][1], bd);
            }
            #pragma unroll
            for (int mt = 0; mt < MT; mt++)
                #pragma unroll
                for (int nt = 0; nt < 4; nt++)
                    mma_f16(acc[mt][nt], a[mt], b[nt]);
        }
        if (t + 2 < NT) issue(t + 2, (t + 2) % 3);
    }

    #pragma unroll
    for (int mt = 0; mt < MT; mt++) {
        #pragma unroll
        for (int nt = 0; nt < 4; nt++) {
            const int row = blockRow + wm * (BM / 2) + mt * 16 + (lane >> 2);
            const int col = blockCol + wn * 32 + nt * 8 + 2 * (lane & 3);
            if (WRITE_F16) {
                float w0 = acc[mt][nt][0] * alpha;
                float w1 = acc[mt][nt][1] * alpha;
                float w2 = acc[mt][nt][2] * alpha;
                float w3 = acc[mt][nt][3] * alpha;
                *(uint32_t*)(Ch + (size_t)row * DD + col)       = pack_f16x2(w0, w1);
                *(uint32_t*)(Ch + (size_t)(row + 8) * DD + col) = pack_f16x2(w2, w3);
            } else {
                float b0 = bias[col], b1 = bias[col + 1];
                float2 v0 = make_float2(acc[mt][nt][0] + b0, acc[mt][nt][1] + b1);
                float2 v1 = make_float2(acc[mt][nt][2] + b0, acc[mt][nt][3] + b1);
                *(float2*)(Cf + (size_t)row * DD + col)       = v0;
                *(float2*)(Cf + (size_t)(row + 8) * DD + col) = v1;
            }
        }
    }
}

// ---------------------------------------------------------------------------
// Launch:  out = x @ (2048*Wv@Wo) + (2048*bv@Wo + bo)
// (encoder_x/Wq/bq/Wk/bk dead: softmax rows sum to 1; the reference einsum
// contracts both q and k, so scores contribute exactly L = 2048.)
// All-fp16 tensor path: W = fp16 GEMM of fp16(Wv),fp16(Wo^T); main GEMM fp16.
// Error budget: main-GEMM ~2.9e-4 (measured R7) (+) W-GEMM ~3.4e-4 -> ~4.5e-4
// aggregate, 2.2x under the 1e-3 gate.
// ---------------------------------------------------------------------------
extern "C" void kernel_launch(void* const* d_in, const int* in_sizes, int n_in,
                              void* d_out, int out_size) {
    const float* x  = (const float*)d_in[0];
    const float* Wv = (const float*)d_in[6];
    const float* bv = (const float*)d_in[7];
    const float* Wo = (const float*)d_in[8];
    const float* bo = (const float*)d_in[9];
    float* out = (float*)d_out;

    unsigned short *xh, *wv16, *wot16, *wt;
    float *c;
    cudaGetSymbolAddress((void**)&xh,    g_xh);
    cudaGetSymbolAddress((void**)&wv16,  g_wv16);
    cudaGetSymbolAddress((void**)&wot16, g_wot16);
    cudaGetSymbolAddress((void**)&wt,    g_wt);
    cudaGetSymbolAddress((void**)&c,     g_c);

    constexpr int SMEM64  = (64 + 128) * 128 * 3;    // 73728
    constexpr int SMEM128 = (128 + 128) * 128 * 3;   // 98304
    cudaFuncSetAttribute(gemm_f16<64, true>,
                         cudaFuncAttributeMaxDynamicSharedMemorySize, SMEM64);
    cudaFuncSetAttribute(gemm_f16<128, false>,
                         cudaFuncAttributeMaxDynamicSharedMemorySize, SMEM128);

    // 1) fused prep: x->fp16, Wv->fp16, Wo^T->fp16, bias vector
    prep_kernel<<<PREP_BLKS, 256>>>((const float4*)x, (const float4*)Wv, Wo, bv, bo,
                                    (uint2*)xh, (uint2*)wv16, wot16, c);

    // 2) WT[n][k] = 2048 * sum_j Wo^T[n][j] * Wv[k][j]  -> fp16
    gemm_f16<64, true><<<dim3(8, 16), 256, SMEM64>>>(
        (const __half*)wot16, (const __half*)wv16, nullptr, nullptr, wt, 2048.0f);

    // 3) out[8192][1024] = x_fp16 @ W + c
    gemm_f16<128, false><<<dim3(8, 64), 256, SMEM128>>>(
        (const __half*)xh, (const __half*)wt, c, out, nullptr, 1.0f);
}